// round 3
// baseline (speedup 1.0000x reference)
#include <cuda_runtime.h>
#include <math.h>

#define Bsz 128
#define PP 196
#define ENCD 2048
#define ATTD 512
#define EMBD 512
#define DECD 512
#define VV 30000
#define LL 22
#define TT 21
#define G4 2048
#define XR 3072   // emb(512) | ctx(2048) | h(512)

// output layout offsets (floats): outputs | caps | dec_lens | alphas | sort_ind
// outputs: 128*21*30000 = 80,640,000
// caps:    128*22       = 2,816
// dec_lens:128
// alphas:  128*21*196   = 526,848
// sort_ind:128
#define O_CAPS  80640000ll
#define O_DLEN  80642816ll
#define O_ALPHA 80642944ll
#define O_SORT  81169792ll

__device__ int   g_sort[Bsz];
__device__ int   g_dlen[Bsz];
__device__ int   g_caps[Bsz * LL];
__device__ float g_attn1[(size_t)Bsz * PP * ATTD];   // 12.8M floats
__device__ float g_attn2[Bsz * ATTD];
__device__ float g_h[Bsz * DECD];
__device__ float g_c[Bsz * DECD];
__device__ float g_x[Bsz * XR];
__device__ float g_gates[Bsz * G4];

__device__ __forceinline__ float sigmf_(float x) { return 1.f / (1.f + expf(-x)); }

// ---------------------------------------------------------------- zeroing
__global__ void zero_out_kernel(float4* out4) {
    const size_t n1 = 20160000u;       // outputs region, float4 count
    const size_t base2 = 20160736u;    // alphas region base (float4) = 80,642,944/4
    const size_t n2 = 131712u;         // alphas float4 count = 526,848/4
    size_t stride = (size_t)gridDim.x * blockDim.x;
    float4 z = make_float4(0.f, 0.f, 0.f, 0.f);
    for (size_t i = (size_t)blockIdx.x * blockDim.x + threadIdx.x; i < n1 + n2; i += stride) {
        size_t k = (i < n1) ? i : (base2 + (i - n1));
        out4[k] = z;
    }
}

__global__ void zero_state_kernel() {
    int stride = gridDim.x * blockDim.x;
    int i0 = blockIdx.x * blockDim.x + threadIdx.x;
    for (int i = i0; i < Bsz * DECD; i += stride) { g_h[i] = 0.f; g_c[i] = 0.f; }
    for (int i = i0; i < Bsz * XR; i += stride) g_x[i] = 0.f;
}

// ---------------------------------------------------------------- sort (stable argsort of -lens)
__global__ void sort_kernel(const int* __restrict__ clen,
                            const int* __restrict__ caps_in,
                            float* __restrict__ out) {
    __shared__ int s_len[Bsz];
    int i = threadIdx.x;
    s_len[i] = clen[i];
    __syncthreads();
    int li = s_len[i];
    int rank = 0;
    for (int j = 0; j < Bsz; j++) {
        int lj = s_len[j];
        rank += (lj > li) || (lj == li && j < i);
    }
    g_sort[rank] = i;
    g_dlen[rank] = li - 1;
    out[O_SORT + rank] = (float)i;
    out[O_DLEN + rank] = (float)(li - 1);
    __syncthreads();
    for (int k = i; k < Bsz * LL; k += Bsz) {
        int b = k / LL, j = k % LL;
        int v = caps_in[g_sort[b] * LL + j];
        g_caps[k] = v;
        out[O_CAPS + k] = (float)v;
    }
}

// ---------------------------------------------------------------- attn1 = enc_sorted @ We + be
// M=25088, N=512, K=2048.  BM=64 BN=64 BK=16, 256 thr, 4x4/thread.
__global__ void attn1_kernel(const float* __restrict__ enc,
                             const float* __restrict__ We,
                             const float* __restrict__ be) {
    __shared__ float As[16][65];
    __shared__ float Bs[16][64];
    int m0 = blockIdx.x * 64;
    int n0 = blockIdx.y * 64;
    int tid = threadIdx.x;
    int tm = tid >> 4, tn = tid & 15;
    int ar = tid >> 4, ak = tid & 15;
    size_t abase[4];
#pragma unroll
    for (int rr = 0; rr < 4; rr++) {
        int m = m0 + ar + rr * 16;
        abase[rr] = (size_t)g_sort[m / PP] * (PP * ENCD) + (size_t)(m % PP) * ENCD;
    }
    int bk = tid >> 6, ba = tid & 63;
    float acc[4][4];
#pragma unroll
    for (int i = 0; i < 4; i++)
#pragma unroll
        for (int j = 0; j < 4; j++) acc[i][j] = 0.f;

    for (int k0 = 0; k0 < ENCD; k0 += 16) {
#pragma unroll
        for (int rr = 0; rr < 4; rr++)
            As[ak][ar + rr * 16] = enc[abase[rr] + k0 + ak];
#pragma unroll
        for (int kk = 0; kk < 4; kk++)
            Bs[bk + kk * 4][ba] = We[(size_t)(k0 + bk + kk * 4) * ATTD + n0 + ba];
        __syncthreads();
#pragma unroll
        for (int kk = 0; kk < 16; kk++) {
            float a[4], b[4];
#pragma unroll
            for (int i = 0; i < 4; i++) a[i] = As[kk][tm * 4 + i];
#pragma unroll
            for (int j = 0; j < 4; j++) b[j] = Bs[kk][tn * 4 + j];
#pragma unroll
            for (int i = 0; i < 4; i++)
#pragma unroll
                for (int j = 0; j < 4; j++) acc[i][j] += a[i] * b[j];
        }
        __syncthreads();
    }
#pragma unroll
    for (int i = 0; i < 4; i++) {
        int m = m0 + tm * 4 + i;
#pragma unroll
        for (int j = 0; j < 4; j++) {
            int n = n0 + tn * 4 + j;
            g_attn1[(size_t)m * ATTD + n] = acc[i][j] + be[n];
        }
    }
}

// ---------------------------------------------------------------- attn2 = h @ Wd + bd  (M=128 N=512 K=512)
__global__ void attn2_kernel(const float* __restrict__ Wd,
                             const float* __restrict__ bd, int t) {
    int m0 = blockIdx.x * 32;
    if (t >= g_dlen[m0]) return;           // rows sorted desc by dec_len
    int n0 = blockIdx.y * 64;
    __shared__ float As[32][33];
    __shared__ float Bs[32][65];
    int tid = threadIdx.x;
    int tm = tid >> 4, tn = tid & 15;
    int lk = tid & 31, lr = tid >> 5;
    int ln = tid & 63, lkk = tid >> 6;
    float acc[2][4];
#pragma unroll
    for (int i = 0; i < 2; i++)
#pragma unroll
        for (int j = 0; j < 4; j++) acc[i][j] = 0.f;

    for (int k0 = 0; k0 < DECD; k0 += 32) {
#pragma unroll
        for (int rr = 0; rr < 4; rr++)
            As[lk][lr + rr * 8] = g_h[(m0 + lr + rr * 8) * DECD + k0 + lk];
#pragma unroll
        for (int kk = 0; kk < 8; kk++)
            Bs[lkk + kk * 4][ln] = Wd[(size_t)(k0 + lkk + kk * 4) * ATTD + n0 + ln];
        __syncthreads();
#pragma unroll
        for (int kk = 0; kk < 32; kk++) {
            float a0 = As[kk][tm * 2], a1 = As[kk][tm * 2 + 1];
            float b0 = Bs[kk][tn * 4 + 0], b1 = Bs[kk][tn * 4 + 1];
            float b2 = Bs[kk][tn * 4 + 2], b3 = Bs[kk][tn * 4 + 3];
            acc[0][0] += a0 * b0; acc[0][1] += a0 * b1; acc[0][2] += a0 * b2; acc[0][3] += a0 * b3;
            acc[1][0] += a1 * b0; acc[1][1] += a1 * b1; acc[1][2] += a1 * b2; acc[1][3] += a1 * b3;
        }
        __syncthreads();
    }
#pragma unroll
    for (int i = 0; i < 2; i++) {
        int b = m0 + tm * 2 + i;
#pragma unroll
        for (int j = 0; j < 4; j++) {
            int n = n0 + tn * 4 + j;
            g_attn2[b * ATTD + n] = acc[i][j] + bd[n];
        }
    }
}

// ---------------------------------------------------------------- fused attention: e, softmax, alpha, ctx, emb gather
__global__ void attention_kernel(const float* __restrict__ enc,
                                 const float* __restrict__ wf,
                                 const float* __restrict__ bfp,
                                 const float* __restrict__ emb_table,
                                 float* __restrict__ out, int t) {
    int b = blockIdx.x;
    if (t >= g_dlen[b]) return;
    int tid = threadIdx.x;
    int warp = tid >> 5, lane = tid & 31;
    __shared__ float s_a2[ATTD];
    __shared__ float s_e[PP];
    __shared__ float s_red[32];

    // embedding gather for this step into x[0:512]
    int cap = g_caps[b * LL + t];
    for (int i = tid; i < EMBD; i += 256)
        g_x[b * XR + i] = emb_table[(size_t)cap * EMBD + i];
    for (int i = tid; i < ATTD; i += 256) s_a2[i] = g_attn2[b * ATTD + i];
    __syncthreads();

    float bfv = bfp[0];
    const float* a1 = g_attn1 + (size_t)b * PP * ATTD;
    for (int p = warp; p < PP; p += 8) {
        const float* row = a1 + (size_t)p * ATTD;
        float s = 0.f;
        for (int a = lane; a < ATTD; a += 32) {
            float v = row[a] + s_a2[a];
            v = fmaxf(v, 0.f);
            s += v * wf[a];
        }
#pragma unroll
        for (int o = 16; o; o >>= 1) s += __shfl_xor_sync(0xffffffffu, s, o);
        if (lane == 0) s_e[p] = s + bfv;
    }
    __syncthreads();

    // softmax over 196
    float mx = -1e30f;
    for (int p = tid; p < PP; p += 256) mx = fmaxf(mx, s_e[p]);
#pragma unroll
    for (int o = 16; o; o >>= 1) mx = fmaxf(mx, __shfl_xor_sync(0xffffffffu, mx, o));
    if (lane == 0) s_red[warp] = mx;
    __syncthreads();
    if (tid == 0) {
        float m2 = s_red[0];
        for (int w = 1; w < 8; w++) m2 = fmaxf(m2, s_red[w]);
        s_red[16] = m2;
    }
    __syncthreads();
    mx = s_red[16];
    float sum = 0.f;
    for (int p = tid; p < PP; p += 256) {
        float e = expf(s_e[p] - mx);
        s_e[p] = e;
        sum += e;
    }
#pragma unroll
    for (int o = 16; o; o >>= 1) sum += __shfl_xor_sync(0xffffffffu, sum, o);
    if (lane == 0) s_red[warp] = sum;
    __syncthreads();
    if (tid == 0) {
        float s2 = 0.f;
        for (int w = 0; w < 8; w++) s2 += s_red[w];
        s_red[17] = 1.f / s2;
    }
    __syncthreads();
    float inv = s_red[17];
    float* aout = out + O_ALPHA + ((size_t)b * TT + t) * PP;
    for (int p = tid; p < PP; p += 256) {
        float al = s_e[p] * inv;
        s_e[p] = al;
        aout[p] = al;
    }
    __syncthreads();

    // ctx[e] = sum_p alpha[p] * enc[b,p,e]  -> x[512:2560]
    const float* encb = enc + (size_t)g_sort[b] * (PP * ENCD);
    float acc[8];
#pragma unroll
    for (int j = 0; j < 8; j++) acc[j] = 0.f;
    for (int p = 0; p < PP; p++) {
        float al = s_e[p];
        const float* er = encb + (size_t)p * ENCD;
#pragma unroll
        for (int j = 0; j < 8; j++) acc[j] += al * er[tid + 256 * j];
    }
    float* xo = g_x + b * XR + EMBD;
#pragma unroll
    for (int j = 0; j < 8; j++) xo[tid + 256 * j] = acc[j];
}

// ---------------------------------------------------------------- gates = x@Wih^T + h@Whh^T + biases (M=128 N=2048 K=3072)
__global__ void gates_kernel(const float* __restrict__ Wih, const float* __restrict__ bih,
                             const float* __restrict__ Whh, const float* __restrict__ bhh, int t) {
    int m0 = blockIdx.x * 32;
    if (t >= g_dlen[m0]) return;
    int n0 = blockIdx.y * 64;
    __shared__ float As[32][33];
    __shared__ float Bs[32][65];
    int tid = threadIdx.x;
    int tm = tid >> 4, tn = tid & 15;
    int lk = tid & 31, lr = tid >> 5;
    int bkk = tid & 31, bj = tid >> 5;   // 0..7
    float acc[2][4];
#pragma unroll
    for (int i = 0; i < 2; i++)
#pragma unroll
        for (int j = 0; j < 4; j++) acc[i][j] = 0.f;

    for (int k0 = 0; k0 < XR; k0 += 32) {
#pragma unroll
        for (int rr = 0; rr < 4; rr++)
            As[lk][lr + rr * 8] = g_x[(m0 + lr + rr * 8) * XR + k0 + lk];
        if (k0 < 2560) {
#pragma unroll
            for (int jj = 0; jj < 8; jj++)
                Bs[bkk][bj + jj * 8] = Wih[(size_t)(n0 + bj + jj * 8) * 2560 + k0 + bkk];
        } else {
#pragma unroll
            for (int jj = 0; jj < 8; jj++)
                Bs[bkk][bj + jj * 8] = Whh[(size_t)(n0 + bj + jj * 8) * DECD + (k0 - 2560) + bkk];
        }
        __syncthreads();
#pragma unroll
        for (int kk = 0; kk < 32; kk++) {
            float a0 = As[kk][tm * 2], a1 = As[kk][tm * 2 + 1];
            float b0 = Bs[kk][tn * 4 + 0], b1 = Bs[kk][tn * 4 + 1];
            float b2 = Bs[kk][tn * 4 + 2], b3 = Bs[kk][tn * 4 + 3];
            acc[0][0] += a0 * b0; acc[0][1] += a0 * b1; acc[0][2] += a0 * b2; acc[0][3] += a0 * b3;
            acc[1][0] += a1 * b0; acc[1][1] += a1 * b1; acc[1][2] += a1 * b2; acc[1][3] += a1 * b3;
        }
        __syncthreads();
    }
#pragma unroll
    for (int i = 0; i < 2; i++) {
        int b = m0 + tm * 2 + i;
#pragma unroll
        for (int j = 0; j < 4; j++) {
            int jn = n0 + tn * 4 + j;
            g_gates[b * G4 + jn] = acc[i][j] + bih[jn] + bhh[jn];
        }
    }
}

// ---------------------------------------------------------------- LSTM pointwise (masked update)
__global__ void lstm_kernel(int t) {
    int idx = blockIdx.x * blockDim.x + threadIdx.x;
    if (idx >= Bsz * DECD) return;
    int b = idx >> 9;
    if (t >= g_dlen[b]) return;
    int d = idx & 511;
    const float* gr = g_gates + (size_t)b * G4;
    float gi = gr[d], gf = gr[d + 512], gg = gr[d + 1024], go = gr[d + 1536];
    float c = g_c[idx];
    float cn = sigmf_(gf) * c + sigmf_(gi) * tanhf(gg);
    float hn = sigmf_(go) * tanhf(cn);
    g_c[idx] = cn;
    g_h[idx] = hn;                 // active => h == h_new
    g_x[b * XR + 2560 + d] = hn;   // h slot of gates input for next step
}

// ---------------------------------------------------------------- fc: out[b,t,:] = h@Wfc + bfc  (M=128 N=30000 K=512)
__global__ void fc_kernel(const float* __restrict__ Wfc, const float* __restrict__ bfc,
                          float* __restrict__ out, int t) {
    int m0 = blockIdx.x * 32;
    if (t >= g_dlen[m0]) return;
    int n0 = blockIdx.y * 64;
    __shared__ float As[32][33];
    __shared__ float Bs[32][65];
    int tid = threadIdx.x;
    int tm = tid >> 4, tn = tid & 15;
    int lk = tid & 31, lr = tid >> 5;
    int ln = tid & 63, lkk = tid >> 6;
    float acc[2][4];
#pragma unroll
    for (int i = 0; i < 2; i++)
#pragma unroll
        for (int j = 0; j < 4; j++) acc[i][j] = 0.f;

    for (int k0 = 0; k0 < DECD; k0 += 32) {
#pragma unroll
        for (int rr = 0; rr < 4; rr++)
            As[lk][lr + rr * 8] = g_h[(m0 + lr + rr * 8) * DECD + k0 + lk];
#pragma unroll
        for (int kk = 0; kk < 8; kk++) {
            int n = n0 + ln;
            Bs[lkk + kk * 4][ln] = (n < VV) ? Wfc[(size_t)(k0 + lkk + kk * 4) * VV + n] : 0.f;
        }
        __syncthreads();
#pragma unroll
        for (int kk = 0; kk < 32; kk++) {
            float a0 = As[kk][tm * 2], a1 = As[kk][tm * 2 + 1];
            float b0 = Bs[kk][tn * 4 + 0], b1 = Bs[kk][tn * 4 + 1];
            float b2 = Bs[kk][tn * 4 + 2], b3 = Bs[kk][tn * 4 + 3];
            acc[0][0] += a0 * b0; acc[0][1] += a0 * b1; acc[0][2] += a0 * b2; acc[0][3] += a0 * b3;
            acc[1][0] += a1 * b0; acc[1][1] += a1 * b1; acc[1][2] += a1 * b2; acc[1][3] += a1 * b3;
        }
        __syncthreads();
    }
#pragma unroll
    for (int i = 0; i < 2; i++) {
        int b = m0 + tm * 2 + i;
        if (t < g_dlen[b]) {
            float* ob = out + ((size_t)b * TT + t) * VV;
#pragma unroll
            for (int j = 0; j < 4; j++) {
                int n = n0 + tn * 4 + j;
                if (n < VV) ob[n] = acc[i][j] + bfc[n];
            }
        }
    }
}

// ---------------------------------------------------------------- launch
extern "C" void kernel_launch(void* const* d_in, const int* in_sizes, int n_in,
                              void* d_out, int out_size) {
    const float* enc  = (const float*)d_in[0];
    const int*   caps = (const int*)d_in[1];
    const int*   clen = (const int*)d_in[2];
    const float* embt = (const float*)d_in[3];
    const float* We   = (const float*)d_in[4];
    const float* be   = (const float*)d_in[5];
    const float* Wd   = (const float*)d_in[6];
    const float* bd   = (const float*)d_in[7];
    const float* wf   = (const float*)d_in[8];
    const float* bf   = (const float*)d_in[9];
    const float* Wih  = (const float*)d_in[10];
    const float* bih  = (const float*)d_in[11];
    const float* Whh  = (const float*)d_in[12];
    const float* bhh  = (const float*)d_in[13];
    const float* Wfc  = (const float*)d_in[14];
    const float* bfc  = (const float*)d_in[15];
    float* out = (float*)d_out;

    zero_out_kernel<<<8192, 256>>>((float4*)out);
    zero_state_kernel<<<512, 256>>>();
    sort_kernel<<<1, 128>>>(clen, caps, out);
    attn1_kernel<<<dim3(392, 8), 256>>>(enc, We, be);

    for (int t = 0; t < TT; t++) {
        attn2_kernel<<<dim3(4, 8), 256>>>(Wd, bd, t);
        attention_kernel<<<128, 256>>>(enc, wf, bf, embt, out, t);
        gates_kernel<<<dim3(4, 32), 256>>>(Wih, bih, Whh, bhh, t);
        lstm_kernel<<<256, 256>>>(t);
        fc_kernel<<<dim3(4, 469), 256>>>(Wfc, bfc, out, t);
    }
}

// round 9
// speedup vs baseline: 1.9111x; 1.9111x over previous
#include <cuda_runtime.h>
#include <cuda_bf16.h>
#include <mma.h>
#include <math.h>
#include <stdint.h>

using namespace nvcuda;

#define Bsz 128
#define PP 196
#define ENCD 2048
#define ATTD 512
#define EMBD 512
#define DECD 512
#define VV 30000
#define LL 22
#define TT 21
#define G4 2048
#define XR 3072   // emb(512) | ctx(2048) | h(512)

// output layout offsets (floats): outputs | caps | dec_lens | alphas | sort_ind
#define O_CAPS  80640000ll
#define O_DLEN  80642816ll
#define O_ALPHA 80642944ll
#define O_SORT  81169792ll

__device__ int   g_sort[Bsz];
__device__ int   g_dlen[Bsz];
__device__ int   g_caps[Bsz * LL];
__device__ __align__(16) float g_attn1[(size_t)Bsz * PP * ATTD];
__device__ __align__(16) float g_attn2[Bsz * ATTD];
__device__ __align__(16) float g_h[Bsz * DECD];
__device__ __align__(16) float g_c[Bsz * DECD];
__device__ __align__(16) float g_x[Bsz * XR];
__device__ __align__(16) float g_gpart[3][Bsz * G4];

__device__ __forceinline__ float sigmf_(float x) { return 1.f / (1.f + expf(-x)); }

__device__ __forceinline__ uint32_t pack_hi2(float x, float y) {
    __nv_bfloat162 t;
    t.x = __float2bfloat16(x);
    t.y = __float2bfloat16(y);
    return *reinterpret_cast<uint32_t*>(&t);
}
__device__ __forceinline__ uint32_t pack_lo2(float x, float y) {
    __nv_bfloat16 hx = __float2bfloat16(x), hy = __float2bfloat16(y);
    __nv_bfloat162 t;
    t.x = __float2bfloat16(x - __bfloat162float(hx));
    t.y = __float2bfloat16(y - __bfloat162float(hy));
    return *reinterpret_cast<uint32_t*>(&t);
}

// ================= setup kernels =================
__global__ void zero_out_kernel(float4* out4) {
    const size_t n1 = 20160000u;
    const size_t base2 = 20160736u;
    const size_t n2 = 131712u;
    size_t stride = (size_t)gridDim.x * blockDim.x;
    float4 z = make_float4(0.f, 0.f, 0.f, 0.f);
    for (size_t i = (size_t)blockIdx.x * blockDim.x + threadIdx.x; i < n1 + n2; i += stride) {
        size_t k = (i < n1) ? i : (base2 + (i - n1));
        out4[k] = z;
    }
}

__global__ void zero_state_kernel() {
    int stride = gridDim.x * blockDim.x;
    int i0 = blockIdx.x * blockDim.x + threadIdx.x;
    for (int i = i0; i < Bsz * DECD; i += stride) { g_h[i] = 0.f; g_c[i] = 0.f; }
    for (int i = i0; i < Bsz * XR; i += stride) g_x[i] = 0.f;
}

__global__ void sort_kernel(const int* __restrict__ clen,
                            const int* __restrict__ caps_in,
                            float* __restrict__ out) {
    __shared__ int s_len[Bsz];
    int i = threadIdx.x;
    s_len[i] = clen[i];
    __syncthreads();
    int li = s_len[i];
    int rank = 0;
    for (int j = 0; j < Bsz; j++) {
        int lj = s_len[j];
        rank += (lj > li) || (lj == li && j < i);
    }
    g_sort[rank] = i;
    g_dlen[rank] = li - 1;
    out[O_SORT + rank] = (float)i;
    out[O_DLEN + rank] = (float)(li - 1);
    __syncthreads();
    for (int k = i; k < Bsz * LL; k += Bsz) {
        int b = k / LL, j = k % LL;
        int v = caps_in[g_sort[b] * LL + j];
        g_caps[k] = v;
        out[O_CAPS + k] = (float)v;
    }
}

// ================= WMMA GEMM =================
// C[128 x 64] per block; K chunks of 32; bf16 hi/lo 3-pass; fp32 accum.
// B converted on the fly from original fp32 weights:
//   MODE 0: attn1  A=enc(gathered)  B=We  [ENCD][ATTD] (K-major rows, transpose in staging)
//   MODE 1: attn2  A=g_h            B=Wd  [DECD][ATTD]
//   MODE 2: gates  A=g_x            B=Wih [2048][2560] & Whh [2048][512] (already [N][K], direct)
//   MODE 3: fc     A=g_h            B=Wfc [DECD][VV], out=outputs (+bfc, row-masked)
// smem: sA_hi [128][40]bf16 | sA_lo | sB_hi [64][40]bf16 | sB_lo  (30720B of 32768B);
// epilogue reuses the buffer as 8x [32][32] f32 staging.
template<int MODE, int KTOT, int KLEN, int NST>
__global__ void __launch_bounds__(256)
mma_gemm(const float* __restrict__ Afp,
         const float* __restrict__ W1, const float* __restrict__ W2,
         const float* __restrict__ b1,
         float* __restrict__ op, int t) {
    __shared__ __align__(16) char smem_raw[32768];
    __nv_bfloat16* sA_hi = (__nv_bfloat16*)smem_raw;   // [128][40]
    __nv_bfloat16* sA_lo = sA_hi + 5120;
    __nv_bfloat16* sB_hi = sA_hi + 10240;              // [64][40]
    __nv_bfloat16* sB_lo = sA_hi + 12800;

    int tid = threadIdx.x, lane = tid & 31, wid = tid >> 5;
    int wm = wid >> 1, wn = wid & 1;
    int n0 = blockIdx.x * 64;
    int m0 = (MODE == 0) ? (int)blockIdx.y * 128 : 0;
    int ks = (MODE == 2) ? (int)blockIdx.y : 0;
    int kbase = ks * KLEN;
    constexpr int NC = KLEN / 32;

    // A row pointers (fp32 sources)
    int arow_s = tid >> 3, ac4 = tid & 7;
    const float* aptr[4];
#pragma unroll
    for (int j = 0; j < 4; j++) {
        int row = arow_s + j * 32;
        if constexpr (MODE == 0) {
            int mg = m0 + row;
            aptr[j] = Afp + (size_t)g_sort[mg / PP] * (PP * ENCD) + (size_t)(mg % PP) * ENCD + kbase + ac4 * 4;
        } else if constexpr (MODE == 2) {
            aptr[j] = g_x + (size_t)row * XR + kbase + ac4 * 4;
        } else {
            aptr[j] = g_h + (size_t)row * DECD + kbase + ac4 * 4;
        }
    }
    int offAe[4];
#pragma unroll
    for (int j = 0; j < 4; j++) offAe[j] = (arow_s + j * 32) * 40 + ac4 * 4;

    wmma::fragment<wmma::accumulator, 16, 16, 16, float> C[2][2];
#pragma unroll
    for (int a = 0; a < 2; a++)
#pragma unroll
        for (int b = 0; b < 2; b++) wmma::fill_fragment(C[a][b], 0.f);

#pragma unroll 1
    for (int c = 0; c < NC; c++) {
        int kc = c * 32;
        // ---- stage A (fp32 -> bf16 hi/lo) ----
#pragma unroll
        for (int j = 0; j < 4; j++) {
            float4 v = *(const float4*)(aptr[j] + kc);
            *(uint2*)(sA_hi + offAe[j]) = make_uint2(pack_hi2(v.x, v.y), pack_hi2(v.z, v.w));
            *(uint2*)(sA_lo + offAe[j]) = make_uint2(pack_lo2(v.x, v.y), pack_lo2(v.z, v.w));
        }
        // ---- stage B ----
        if constexpr (MODE == 2) {
            // W already [N][K]: direct rows, Wih then Whh
#pragma unroll
            for (int r = 0; r < 2; r++) {
                int idx = tid + 256 * r;          // 0..511
                int row = idx >> 3, c4 = idx & 7; // 64 rows x 8 float4
                int kg = kbase + kc + c4 * 4;
                const float* src = (kg < 2560) ? W1 + (size_t)(n0 + row) * 2560 + kg
                                               : W2 + (size_t)(n0 + row) * 512 + (kg - 2560);
                float4 v = *(const float4*)src;
                int o = row * 40 + c4 * 4;
                *(uint2*)(sB_hi + o) = make_uint2(pack_hi2(v.x, v.y), pack_hi2(v.z, v.w));
                *(uint2*)(sB_lo + o) = make_uint2(pack_lo2(v.x, v.y), pack_lo2(v.z, v.w));
            }
        } else {
            // W is [K][NST]: load 32k x 64n slab, transpose into [n][k]
#pragma unroll
            for (int r = 0; r < 2; r++) {
                int idx = tid + 256 * r;          // 0..511
                int k = idx >> 4, nf4 = idx & 15; // 32 k-rows x 16 float4
                int n = nf4 * 4;
                float4 v = make_float4(0.f, 0.f, 0.f, 0.f);
                bool ok = (MODE != 3) || (n0 + n < NST);
                if (ok) v = *(const float4*)(W1 + (size_t)(kbase + kc + k) * NST + n0 + n);
                float vv[4] = {v.x, v.y, v.z, v.w};
#pragma unroll
                for (int i = 0; i < 4; i++) {
                    __nv_bfloat16 h = __float2bfloat16(vv[i]);
                    sB_hi[(n + i) * 40 + k] = h;
                    sB_lo[(n + i) * 40 + k] = __float2bfloat16(vv[i] - __bfloat162float(h));
                }
            }
        }
        __syncthreads();

        // ---- compute: 2 k16 steps, 3-pass hi/lo ----
#pragma unroll
        for (int kk = 0; kk < 2; kk++) {
#pragma unroll
            for (int mf = 0; mf < 2; mf++) {
                wmma::fragment<wmma::matrix_a, 16, 16, 16, __nv_bfloat16, wmma::row_major> aH, aL;
                wmma::load_matrix_sync(aH, sA_hi + (wm * 32 + mf * 16) * 40 + kk * 16, 40);
                wmma::load_matrix_sync(aL, sA_lo + (wm * 32 + mf * 16) * 40 + kk * 16, 40);
#pragma unroll
                for (int nf = 0; nf < 2; nf++) {
                    wmma::fragment<wmma::matrix_b, 16, 16, 16, __nv_bfloat16, wmma::col_major> bH, bL;
                    wmma::load_matrix_sync(bH, sB_hi + (wn * 32 + nf * 16) * 40 + kk * 16, 40);
                    wmma::load_matrix_sync(bL, sB_lo + (wn * 32 + nf * 16) * 40 + kk * 16, 40);
                    wmma::mma_sync(C[mf][nf], aH, bH, C[mf][nf]);
                    wmma::mma_sync(C[mf][nf], aH, bL, C[mf][nf]);
                    wmma::mma_sync(C[mf][nf], aL, bH, C[mf][nf]);
                }
            }
        }
        __syncthreads();
    }

    // ---- epilogue: per-warp smem staging then scalar stores ----
    float* stg = (float*)smem_raw + wid * 1024;   // [32][32] per warp
    wmma::store_matrix_sync(stg,               C[0][0], 32, wmma::mem_row_major);
    wmma::store_matrix_sync(stg + 16,          C[0][1], 32, wmma::mem_row_major);
    wmma::store_matrix_sync(stg + 16 * 32,     C[1][0], 32, wmma::mem_row_major);
    wmma::store_matrix_sync(stg + 16 * 32 + 16, C[1][1], 32, wmma::mem_row_major);
    __syncwarp();
#pragma unroll 4
    for (int e = lane; e < 1024; e += 32) {
        int rl = e >> 5, cl = e & 31;
        int gr = wm * 32 + rl;
        int n = n0 + wn * 32 + cl;
        float v = stg[e];
        if constexpr (MODE == 0) {
            g_attn1[(size_t)(m0 + gr) * ATTD + n] = v + b1[n];
        } else if constexpr (MODE == 1) {
            g_attn2[gr * ATTD + n] = v + b1[n];
        } else if constexpr (MODE == 2) {
            g_gpart[ks][gr * G4 + n] = v;
        } else {
            if (t < g_dlen[gr] && n < VV)
                op[((size_t)gr * TT + t) * VV + n] = v + b1[n];
        }
    }
}

// ================= attention (fused e/softmax/alpha/ctx/emb) =================
__global__ void attention_kernel(const float* __restrict__ enc,
                                 const float* __restrict__ wf,
                                 const float* __restrict__ bfp,
                                 const float* __restrict__ emb_table,
                                 float* __restrict__ out, int t) {
    int b = blockIdx.x;
    if (t >= g_dlen[b]) return;
    int tid = threadIdx.x;
    int warp = tid >> 5, lane = tid & 31;
    __shared__ float s_a2[ATTD];
    __shared__ float s_e[PP];
    __shared__ float s_red[32];

    int cap = g_caps[b * LL + t];
    for (int i = tid; i < EMBD; i += 256)
        g_x[b * XR + i] = emb_table[(size_t)cap * EMBD + i];
    for (int i = tid; i < ATTD; i += 256) s_a2[i] = g_attn2[b * ATTD + i];
    __syncthreads();

    float bfv = bfp[0];
    const float* a1 = g_attn1 + (size_t)b * PP * ATTD;
    for (int p = warp; p < PP; p += 8) {
        const float* row = a1 + (size_t)p * ATTD;
        float s = 0.f;
        for (int a = lane; a < ATTD; a += 32) {
            float v = row[a] + s_a2[a];
            v = fmaxf(v, 0.f);
            s += v * wf[a];
        }
#pragma unroll
        for (int o = 16; o; o >>= 1) s += __shfl_xor_sync(0xffffffffu, s, o);
        if (lane == 0) s_e[p] = s + bfv;
    }
    __syncthreads();

    float mx = -1e30f;
    for (int p = tid; p < PP; p += 256) mx = fmaxf(mx, s_e[p]);
#pragma unroll
    for (int o = 16; o; o >>= 1) mx = fmaxf(mx, __shfl_xor_sync(0xffffffffu, mx, o));
    if (lane == 0) s_red[warp] = mx;
    __syncthreads();
    if (tid == 0) {
        float m2 = s_red[0];
        for (int w = 1; w < 8; w++) m2 = fmaxf(m2, s_red[w]);
        s_red[16] = m2;
    }
    __syncthreads();
    mx = s_red[16];
    float sum = 0.f;
    for (int p = tid; p < PP; p += 256) {
        float e = expf(s_e[p] - mx);
        s_e[p] = e;
        sum += e;
    }
#pragma unroll
    for (int o = 16; o; o >>= 1) sum += __shfl_xor_sync(0xffffffffu, sum, o);
    if (lane == 0) s_red[warp] = sum;
    __syncthreads();
    if (tid == 0) {
        float s2 = 0.f;
        for (int w = 0; w < 8; w++) s2 += s_red[w];
        s_red[17] = 1.f / s2;
    }
    __syncthreads();
    float inv = s_red[17];
    float* aout = out + O_ALPHA + ((size_t)b * TT + t) * PP;
    for (int p = tid; p < PP; p += 256) {
        float al = s_e[p] * inv;
        s_e[p] = al;
        aout[p] = al;
    }
    __syncthreads();

    const float* encb = enc + (size_t)g_sort[b] * (PP * ENCD);
    float acc[8];
#pragma unroll
    for (int j = 0; j < 8; j++) acc[j] = 0.f;
    for (int p = 0; p < PP; p++) {
        float al = s_e[p];
        const float* er = encb + (size_t)p * ENCD;
#pragma unroll
        for (int j = 0; j < 8; j++) acc[j] += al * er[tid + 256 * j];
    }
    float* xo = g_x + b * XR + EMBD;
#pragma unroll
    for (int j = 0; j < 8; j++) xo[tid + 256 * j] = acc[j];
}

// ================= LSTM pointwise (sums split-K partials + biases) ===========
__global__ void lstm_kernel(const float* __restrict__ bih, const float* __restrict__ bhh, int t) {
    int idx = blockIdx.x * blockDim.x + threadIdx.x;
    if (idx >= Bsz * DECD) return;
    int b = idx >> 9;
    if (t >= g_dlen[b]) return;
    int d = idx & 511;
    int base = b * G4;
    float gi = g_gpart[0][base + d]        + g_gpart[1][base + d]        + g_gpart[2][base + d]        + bih[d]        + bhh[d];
    float gf = g_gpart[0][base + d + 512]  + g_gpart[1][base + d + 512]  + g_gpart[2][base + d + 512]  + bih[d + 512]  + bhh[d + 512];
    float gg = g_gpart[0][base + d + 1024] + g_gpart[1][base + d + 1024] + g_gpart[2][base + d + 1024] + bih[d + 1024] + bhh[d + 1024];
    float go = g_gpart[0][base + d + 1536] + g_gpart[1][base + d + 1536] + g_gpart[2][base + d + 1536] + bih[d + 1536] + bhh[d + 1536];
    float c = g_c[idx];
    float cn = sigmf_(gf) * c + sigmf_(gi) * tanhf(gg);
    float hn = sigmf_(go) * tanhf(cn);
    g_c[idx] = cn;
    g_h[idx] = hn;
    g_x[b * XR + 2560 + d] = hn;
}

// ================= launch =================
extern "C" void kernel_launch(void* const* d_in, const int* in_sizes, int n_in,
                              void* d_out, int out_size) {
    const float* enc  = (const float*)d_in[0];
    const int*   caps = (const int*)d_in[1];
    const int*   clen = (const int*)d_in[2];
    const float* embt = (const float*)d_in[3];
    const float* We   = (const float*)d_in[4];
    const float* be   = (const float*)d_in[5];
    const float* Wd   = (const float*)d_in[6];
    const float* bd   = (const float*)d_in[7];
    const float* wf   = (const float*)d_in[8];
    const float* bf   = (const float*)d_in[9];
    const float* Wih  = (const float*)d_in[10];
    const float* bih  = (const float*)d_in[11];
    const float* Whh  = (const float*)d_in[12];
    const float* bhh  = (const float*)d_in[13];
    const float* Wfc  = (const float*)d_in[14];
    const float* bfc  = (const float*)d_in[15];
    float* out = (float*)d_out;

    zero_out_kernel<<<8192, 256>>>((float4*)out);
    zero_state_kernel<<<512, 256>>>();
    sort_kernel<<<1, 128>>>(clen, caps, out);

    // attn1 = enc_sorted @ We + be   (M=25088, N=512)
    mma_gemm<0, ENCD, ENCD, ATTD><<<dim3(8, 196), 256>>>(enc, We, nullptr, be, nullptr, 0);

    for (int t = 0; t < TT; t++) {
        mma_gemm<1, DECD, DECD, ATTD><<<dim3(8, 1), 256>>>(nullptr, Wd, nullptr, bd, nullptr, t);
        attention_kernel<<<128, 256>>>(enc, wf, bf, embt, out, t);
        mma_gemm<2, XR, 1024, 1><<<dim3(32, 3), 256>>>(nullptr, Wih, Whh, nullptr, nullptr, t);
        lstm_kernel<<<256, 256>>>(bih, bhh, t);
        mma_gemm<3, DECD, DECD, VV><<<dim3(469, 1), 256>>>(nullptr, Wfc, nullptr, bfc, out, t);
    }
}